// round 2
// baseline (speedup 1.0000x reference)
#include <cuda_runtime.h>
#include <cuda_fp16.h>
#include <cstdint>

#define DEV __device__ __forceinline__

static constexpr int NROWS = 2048;
static constexpr int INF   = 4096;
static constexpr int OUTF  = 4096;

static constexpr int BM = 128, BN = 128, BK = 32;
static constexpr int STAGES = 4;
static constexpr int NIT = INF / BK;                     // 128
static constexpr int PITCH_H = 40;                       // halfs per smem row (32 + 8 pad)
static constexpr int PITCH_B = PITCH_H * 2;              // 80 bytes
static constexpr int A_BYTES = BM * PITCH_B;             // 10240
static constexpr int B_BYTES = BN * PITCH_B;             // 10240
static constexpr int STAGE_BYTES = A_BYTES + B_BYTES;    // 20480
static constexpr int SMEM_ALLOC = STAGES * STAGE_BYTES;  // 81920

// ---------------- scratch (no allocs allowed) ----------------
__device__ __align__(1024) __half g_wmean[(size_t)OUTF * INF];
__device__ __align__(1024) __half g_wvar [(size_t)OUTF * INF];
__device__ __align__(1024) __half g_xh   [(size_t)NROWS * INF];
__device__ __align__(1024) __half g_x2h  [(size_t)NROWS * INF];
__device__ float g_bmean[OUTF];
__device__ float g_bvar [OUTF];

// ---------------- PTX helpers ----------------
DEV uint32_t smem_u32(const void* p) {
    uint32_t a;
    asm("{ .reg .u64 t; cvta.to.shared.u64 t, %1; cvt.u32.u64 %0, t; }" : "=r"(a) : "l"(p));
    return a;
}
DEV void cp16(uint32_t saddr, const void* g) {
    asm volatile("cp.async.cg.shared.global [%0], [%1], 16;" :: "r"(saddr), "l"(g) : "memory");
}
DEV void ldm_x4(uint32_t* r, uint32_t addr) {
    asm volatile("ldmatrix.sync.aligned.m8n8.x4.shared.b16 {%0,%1,%2,%3}, [%4];"
                 : "=r"(r[0]), "=r"(r[1]), "=r"(r[2]), "=r"(r[3]) : "r"(addr));
}
DEV void mma16816(float* c, const uint32_t* a, uint32_t b0, uint32_t b1) {
    asm volatile(
        "mma.sync.aligned.m16n8k16.row.col.f32.f16.f16.f32 "
        "{%0,%1,%2,%3}, {%4,%5,%6,%7}, {%8,%9}, {%0,%1,%2,%3};"
        : "+f"(c[0]), "+f"(c[1]), "+f"(c[2]), "+f"(c[3])
        : "r"(a[0]), "r"(a[1]), "r"(a[2]), "r"(a[3]), "r"(b0), "r"(b1));
}

// ---------------- preprocessing ----------------
DEV void moments(float l0, float l1, float l2, float& mean, float& var) {
    float e0 = __expf(l0), e1 = __expf(l1), e2 = __expf(l2);
    float inv = 1.0f / (e0 + e1 + e2);
    float m  = (e2 - e0) * inv;
    float sq = (e2 + e0) * inv;
    mean = m;
    var  = sq - m * m;
}

__global__ void prep_w_kernel(const float* __restrict__ W) {
    const size_t P = (size_t)OUTF * INF;
    size_t i = ((size_t)blockIdx.x * blockDim.x + threadIdx.x) * 4;
    if (i >= P) return;
    float4 a = *(const float4*)(W + i);
    float4 b = *(const float4*)(W + P + i);
    float4 c = *(const float4*)(W + 2 * P + i);
    float m[4], v[4];
    moments(a.x, b.x, c.x, m[0], v[0]);
    moments(a.y, b.y, c.y, m[1], v[1]);
    moments(a.z, b.z, c.z, m[2], v[2]);
    moments(a.w, b.w, c.w, m[3], v[3]);
    __half2* pm = (__half2*)(g_wmean + i);
    pm[0] = __floats2half2_rn(m[0], m[1]);
    pm[1] = __floats2half2_rn(m[2], m[3]);
    __half2* pv = (__half2*)(g_wvar + i);
    pv[0] = __floats2half2_rn(v[0], v[1]);
    pv[1] = __floats2half2_rn(v[2], v[3]);
}

__global__ void prep_x_kernel(const float* __restrict__ x) {
    const size_t P = (size_t)NROWS * INF;
    size_t i = ((size_t)blockIdx.x * blockDim.x + threadIdx.x) * 4;
    if (i >= P) return;
    float4 a = *(const float4*)(x + i);
    __half2* ph = (__half2*)(g_xh + i);
    ph[0] = __floats2half2_rn(a.x, a.y);
    ph[1] = __floats2half2_rn(a.z, a.w);
    __half2* p2 = (__half2*)(g_x2h + i);
    p2[0] = __floats2half2_rn(a.x * a.x, a.y * a.y);
    p2[1] = __floats2half2_rn(a.z * a.z, a.w * a.w);
}

__global__ void prep_b_kernel(const float* __restrict__ B) {
    int o = blockIdx.x * blockDim.x + threadIdx.x;
    if (o >= OUTF) return;
    float m, v;
    moments(B[o], B[OUTF + o], B[2 * OUTF + o], m, v);
    g_bmean[o] = m;
    g_bvar[o]  = v;
}

// ---------------- GEMM ----------------
DEV void load_stage(char* smem, const char* gA, const char* gB, int cc, int tid) {
    char* sa  = smem + (cc & (STAGES - 1)) * STAGE_BYTES;
    char* sbt = sa + A_BYTES;
    const char* ga = gA + (size_t)cc * (BK * 2);
    const char* gb = gB + (size_t)cc * (BK * 2);
#pragma unroll
    for (int i = 0; i < 2; i++) {
        int idx = tid + i * 256;              // 0..511 over (row, 16B-seg)
        int row = idx >> 2, seg = idx & 3;
        uint32_t so = (uint32_t)(row * PITCH_B + seg * 16);
        size_t   go = (size_t)row * (INF * 2) + (size_t)seg * 16;
        cp16(smem_u32(sa  + so), ga + go);
        cp16(smem_u32(sbt + so), gb + go);
    }
}

__global__ void __launch_bounds__(256, 2)
gemm_kernel(float* __restrict__ out) {
    extern __shared__ char smem[];

    const int tid  = threadIdx.x;
    const int wid  = tid >> 5, lane = tid & 31;
    const int bn = blockIdx.x, bm = blockIdx.y, bz = blockIdx.z;

    const int wm = wid >> 1, wn = wid & 1;    // 4 x 2 warp grid
    const int m0 = wm * 32, n0 = wn * 64;     // warp tile 32 x 64

    const char* gA = (const char*)((bz == 0 ? g_xh    : g_x2h ) + (size_t)bm * BM * INF);
    const char* gB = (const char*)((bz == 0 ? g_wmean : g_wvar) + (size_t)bn * BN * INF);
    const float* bias = (bz == 0 ? g_bmean : g_bvar);

    float acc[2][8][4];
#pragma unroll
    for (int i = 0; i < 2; i++)
#pragma unroll
        for (int j = 0; j < 8; j++)
#pragma unroll
            for (int k = 0; k < 4; k++) acc[i][j][k] = 0.0f;

    // lane-dependent ldmatrix address offsets (bytes within a stage tile)
    const uint32_t a_off = (uint32_t)((m0 + (lane & 15)) * PITCH_B + (lane >> 4) * 16);
    const uint32_t b_off = (uint32_t)((n0 + (lane & 7) + ((lane >> 4) & 1) * 8) * PITCH_B
                                      + ((lane >> 3) & 1) * 16);
    const uint32_t smem_base = smem_u32(smem);

    // prologue: stages 0..2
#pragma unroll
    for (int cc = 0; cc < STAGES - 1; cc++) {
        load_stage(smem, gA, gB, cc, tid);
        asm volatile("cp.async.commit_group;" ::: "memory");
    }

    for (int it = 0; it < NIT; it++) {
        asm volatile("cp.async.wait_group %0;" :: "n"(STAGES - 2) : "memory");
        __syncthreads();

        const int cc = it + STAGES - 1;
        if (cc < NIT) load_stage(smem, gA, gB, cc, tid);
        asm volatile("cp.async.commit_group;" ::: "memory");

        const uint32_t sa_u = smem_base + (uint32_t)((it & (STAGES - 1)) * STAGE_BYTES);
        const uint32_t sb_u = sa_u + A_BYTES;

#pragma unroll
        for (int kk = 0; kk < 2; kk++) {      // two k16 steps in BK=32
            uint32_t a[2][4], b[4][4];
#pragma unroll
            for (int mb = 0; mb < 2; mb++)
                ldm_x4(a[mb], sa_u + a_off + (uint32_t)(mb * 16 * PITCH_B + kk * 32));
#pragma unroll
            for (int nb = 0; nb < 4; nb++)
                ldm_x4(b[nb], sb_u + b_off + (uint32_t)(nb * 16 * PITCH_B + kk * 32));
#pragma unroll
            for (int mb = 0; mb < 2; mb++)
#pragma unroll
                for (int nb = 0; nb < 4; nb++) {
                    mma16816(acc[mb][2 * nb],     a[mb], b[nb][0], b[nb][1]);
                    mma16816(acc[mb][2 * nb + 1], a[mb], b[nb][2], b[nb][3]);
                }
        }
    }

    // epilogue: direct float2 stores with bias
    const int qr = lane >> 2, qc = lane & 3;
    const size_t row_stride = 2 * (size_t)OUTF;
#pragma unroll
    for (int mf = 0; mf < 2; mf++) {
        const int gm = bm * BM + m0 + mf * 16 + qr;
#pragma unroll
        for (int nf = 0; nf < 8; nf++) {
            const int gn = bn * BN + n0 + nf * 8 + qc * 2;
            const float2 bv = *(const float2*)(bias + gn);
            float* p0 = out + (size_t)gm * row_stride + (size_t)bz * OUTF + gn;
            float* p1 = p0 + 8 * row_stride;
            float2 v0 = { acc[mf][nf][0] + bv.x, acc[mf][nf][1] + bv.y };
            float2 v1 = { acc[mf][nf][2] + bv.x, acc[mf][nf][3] + bv.y };
            *(float2*)p0 = v0;
            *(float2*)p1 = v1;
        }
    }
}

// ---------------- launch ----------------
extern "C" void kernel_launch(void* const* d_in, const int* in_sizes, int n_in,
                              void* d_out, int out_size) {
    const float *x = nullptr, *W = nullptr, *Bl = nullptr;
    for (int i = 0; i < n_in; i++) {
        long long s = in_sizes[i];
        if (s == (long long)NROWS * INF)          x  = (const float*)d_in[i];
        else if (s == 3LL * OUTF * INF)           W  = (const float*)d_in[i];
        else if (s == 3LL * OUTF)                 Bl = (const float*)d_in[i];
    }
    float* out = (float*)d_out;

    prep_w_kernel<<<(unsigned)(((size_t)OUTF * INF / 4 + 255) / 256), 256>>>(W);
    prep_x_kernel<<<(unsigned)(((size_t)NROWS * INF / 4 + 255) / 256), 256>>>(x);
    prep_b_kernel<<<(OUTF + 255) / 256, 256>>>(Bl);

    cudaFuncSetAttribute(gemm_kernel, cudaFuncAttributeMaxDynamicSharedMemorySize, SMEM_ALLOC);
    dim3 grid(OUTF / BN, NROWS / BM, 2);  // (32, 16, 2) = 1024 CTAs
    gemm_kernel<<<grid, 256, SMEM_ALLOC>>>(out);
}

// round 3
// speedup vs baseline: 1.2371x; 1.2371x over previous
#include <cuda_runtime.h>
#include <cuda_fp16.h>
#include <cstdint>

#define DEV __device__ __forceinline__

static constexpr int NROWS = 2048;
static constexpr int INF   = 4096;
static constexpr int OUTF  = 4096;

static constexpr int BM = 128, BN = 128, BK = 32;
static constexpr int STAGES = 4;
static constexpr int NIT = INF / BK;                     // 128
static constexpr int PITCH_H = 40;                       // halfs per smem row (32 + 8 pad)
static constexpr int PITCH_B = PITCH_H * 2;              // 80 bytes
static constexpr int A_BYTES = BM * PITCH_B;             // 10240
static constexpr int B_BYTES = BN * PITCH_B;             // 10240
static constexpr int STAGE_BYTES = A_BYTES + B_BYTES;    // 20480
static constexpr int SMEM_ALLOC = STAGES * STAGE_BYTES;  // 81920

// ---------------- scratch (no allocs allowed) ----------------
__device__ __align__(1024) __half g_wmean[(size_t)OUTF * INF];
__device__ __align__(1024) __half g_wvar [(size_t)OUTF * INF];
__device__ __align__(1024) __half g_xh   [(size_t)NROWS * INF];
__device__ __align__(1024) __half g_x2h  [(size_t)NROWS * INF];
__device__ float g_bmean[OUTF];
__device__ float g_bvar [OUTF];

// ---------------- PTX helpers ----------------
DEV uint32_t smem_u32(const void* p) {
    uint32_t a;
    asm("{ .reg .u64 t; cvta.to.shared.u64 t, %1; cvt.u32.u64 %0, t; }" : "=r"(a) : "l"(p));
    return a;
}
DEV void cp16(uint32_t saddr, const void* g) {
    asm volatile("cp.async.cg.shared.global [%0], [%1], 16;" :: "r"(saddr), "l"(g) : "memory");
}
DEV void ldm_x4(uint32_t* r, uint32_t addr) {
    asm volatile("ldmatrix.sync.aligned.m8n8.x4.shared.b16 {%0,%1,%2,%3}, [%4];"
                 : "=r"(r[0]), "=r"(r[1]), "=r"(r[2]), "=r"(r[3]) : "r"(addr));
}
DEV void mma16816(float* c, const uint32_t* a, uint32_t b0, uint32_t b1) {
    asm volatile(
        "mma.sync.aligned.m16n8k16.row.col.f32.f16.f16.f32 "
        "{%0,%1,%2,%3}, {%4,%5,%6,%7}, {%8,%9}, {%0,%1,%2,%3};"
        : "+f"(c[0]), "+f"(c[1]), "+f"(c[2]), "+f"(c[3])
        : "r"(a[0]), "r"(a[1]), "r"(a[2]), "r"(a[3]), "r"(b0), "r"(b1));
}

// ---------------- preprocessing ----------------
DEV void moments(float l0, float l1, float l2, float& mean, float& var) {
    float e0 = __expf(l0), e1 = __expf(l1), e2 = __expf(l2);
    float inv = 1.0f / (e0 + e1 + e2);
    float m  = (e2 - e0) * inv;
    float sq = (e2 + e0) * inv;
    mean = m;
    var  = sq - m * m;
}

__global__ void prep_w_kernel(const float* __restrict__ W) {
    const size_t P = (size_t)OUTF * INF;
    size_t i = ((size_t)blockIdx.x * blockDim.x + threadIdx.x) * 4;
    if (i >= P) return;
    float4 a = *(const float4*)(W + i);
    float4 b = *(const float4*)(W + P + i);
    float4 c = *(const float4*)(W + 2 * P + i);
    float m[4], v[4];
    moments(a.x, b.x, c.x, m[0], v[0]);
    moments(a.y, b.y, c.y, m[1], v[1]);
    moments(a.z, b.z, c.z, m[2], v[2]);
    moments(a.w, b.w, c.w, m[3], v[3]);
    __half2* pm = (__half2*)(g_wmean + i);
    pm[0] = __floats2half2_rn(m[0], m[1]);
    pm[1] = __floats2half2_rn(m[2], m[3]);
    __half2* pv = (__half2*)(g_wvar + i);
    pv[0] = __floats2half2_rn(v[0], v[1]);
    pv[1] = __floats2half2_rn(v[2], v[3]);
}

__global__ void prep_x_kernel(const float* __restrict__ x) {
    const size_t P = (size_t)NROWS * INF;
    size_t i = ((size_t)blockIdx.x * blockDim.x + threadIdx.x) * 4;
    if (i >= P) return;
    float4 a = *(const float4*)(x + i);
    __half2* ph = (__half2*)(g_xh + i);
    ph[0] = __floats2half2_rn(a.x, a.y);
    ph[1] = __floats2half2_rn(a.z, a.w);
    __half2* p2 = (__half2*)(g_x2h + i);
    p2[0] = __floats2half2_rn(a.x * a.x, a.y * a.y);
    p2[1] = __floats2half2_rn(a.z * a.z, a.w * a.w);
}

__global__ void prep_b_kernel(const float* __restrict__ B) {
    int o = blockIdx.x * blockDim.x + threadIdx.x;
    if (o >= OUTF) return;
    float m, v;
    moments(B[o], B[OUTF + o], B[2 * OUTF + o], m, v);
    g_bmean[o] = m;
    g_bvar[o]  = v;
}

// ---------------- GEMM ----------------
DEV void load_stage(char* smem, const char* gA, const char* gB, int cc, int tid) {
    char* sa  = smem + (cc & (STAGES - 1)) * STAGE_BYTES;
    char* sbt = sa + A_BYTES;
    const char* ga = gA + (size_t)cc * (BK * 2);
    const char* gb = gB + (size_t)cc * (BK * 2);
#pragma unroll
    for (int i = 0; i < 2; i++) {
        int idx = tid + i * 256;              // 0..511 over (row, 16B-seg)
        int row = idx >> 2, seg = idx & 3;
        uint32_t so = (uint32_t)(row * PITCH_B + seg * 16);
        size_t   go = (size_t)row * (INF * 2) + (size_t)seg * 16;
        cp16(smem_u32(sa  + so), ga + go);
        cp16(smem_u32(sbt + so), gb + go);
    }
}

__global__ void __launch_bounds__(256, 2)
gemm_kernel(float* __restrict__ out) {
    extern __shared__ char smem[];

    const int tid  = threadIdx.x;
    const int wid  = tid >> 5, lane = tid & 31;
    const int bn = blockIdx.x, bm = blockIdx.y, bz = blockIdx.z;

    const int wm = wid >> 1, wn = wid & 1;    // 4 x 2 warp grid
    const int m0 = wm * 32, n0 = wn * 64;     // warp tile 32 x 64

    const char* gA = (const char*)((bz == 0 ? g_xh    : g_x2h ) + (size_t)bm * BM * INF);
    const char* gB = (const char*)((bz == 0 ? g_wmean : g_wvar) + (size_t)bn * BN * INF);
    const float* bias = (bz == 0 ? g_bmean : g_bvar);

    float acc[2][8][4];
#pragma unroll
    for (int i = 0; i < 2; i++)
#pragma unroll
        for (int j = 0; j < 8; j++)
#pragma unroll
            for (int k = 0; k < 4; k++) acc[i][j][k] = 0.0f;

    // lane-dependent ldmatrix address offsets (bytes within a stage tile)
    const uint32_t a_off = (uint32_t)((m0 + (lane & 15)) * PITCH_B + (lane >> 4) * 16);
    const uint32_t b_off = (uint32_t)(A_BYTES + (n0 + (lane & 7) + ((lane >> 4) & 1) * 8) * PITCH_B
                                      + ((lane >> 3) & 1) * 16);
    const uint32_t smem_base = smem_u32(smem);

    // double-buffered register fragments
    uint32_t afr[2][2][4];
    uint32_t bfr[2][4][4];

    // prologue: stages 0..2 in flight
#pragma unroll
    for (int cc = 0; cc < STAGES - 1; cc++) {
        load_stage(smem, gA, gB, cc, tid);
        asm volatile("cp.async.commit_group;" ::: "memory");
    }
    asm volatile("cp.async.wait_group 2;" ::: "memory");
    __syncthreads();

    // fragments for (stage 0, k-step 0) into buffer 0
#pragma unroll
    for (int mb = 0; mb < 2; mb++)
        ldm_x4(afr[0][mb], smem_base + a_off + (uint32_t)(mb * 16 * PITCH_B));
#pragma unroll
    for (int nb = 0; nb < 4; nb++)
        ldm_x4(bfr[0][nb], smem_base + b_off + (uint32_t)(nb * 16 * PITCH_B));

#pragma unroll 1
    for (int it = 0; it < NIT; it++) {
        const uint32_t sa_u = smem_base + (uint32_t)((it & (STAGES - 1)) * STAGE_BYTES);

        // ---- k-step 0: prefetch k-step 1 frags into buf1, MMA on buf0 ----
#pragma unroll
        for (int mb = 0; mb < 2; mb++)
            ldm_x4(afr[1][mb], sa_u + a_off + (uint32_t)(mb * 16 * PITCH_B + 32));
#pragma unroll
        for (int nb = 0; nb < 4; nb++)
            ldm_x4(bfr[1][nb], sa_u + b_off + (uint32_t)(nb * 16 * PITCH_B + 32));
#pragma unroll
        for (int mb = 0; mb < 2; mb++)
#pragma unroll
            for (int nb = 0; nb < 4; nb++) {
                mma16816(acc[mb][2 * nb],     afr[0][mb], bfr[0][nb][0], bfr[0][nb][1]);
                mma16816(acc[mb][2 * nb + 1], afr[0][mb], bfr[0][nb][2], bfr[0][nb][3]);
            }

        // ---- k-step 1: advance pipeline, prefetch next stage k0 into buf0,
        //      MMA on buf1 (all current-stage smem reads already in regs) ----
        const int cc = it + STAGES - 1;
        if (cc < NIT) load_stage(smem, gA, gB, cc, tid);
        asm volatile("cp.async.commit_group;" ::: "memory");
        asm volatile("cp.async.wait_group 2;" ::: "memory");
        __syncthreads();

        const uint32_t nx_u = smem_base + (uint32_t)(((it + 1) & (STAGES - 1)) * STAGE_BYTES);
#pragma unroll
        for (int mb = 0; mb < 2; mb++)
            ldm_x4(afr[0][mb], nx_u + a_off + (uint32_t)(mb * 16 * PITCH_B));
#pragma unroll
        for (int nb = 0; nb < 4; nb++)
            ldm_x4(bfr[0][nb], nx_u + b_off + (uint32_t)(nb * 16 * PITCH_B));
#pragma unroll
        for (int mb = 0; mb < 2; mb++)
#pragma unroll
            for (int nb = 0; nb < 4; nb++) {
                mma16816(acc[mb][2 * nb],     afr[1][mb], bfr[1][nb][0], bfr[1][nb][1]);
                mma16816(acc[mb][2 * nb + 1], afr[1][mb], bfr[1][nb][2], bfr[1][nb][3]);
            }
    }

    // epilogue: direct float2 stores with bias
    const int qr = lane >> 2, qc = lane & 3;
    const size_t row_stride = 2 * (size_t)OUTF;
#pragma unroll
    for (int mf = 0; mf < 2; mf++) {
        const int gm = bm * BM + m0 + mf * 16 + qr;
#pragma unroll
        for (int nf = 0; nf < 8; nf++) {
            const int gn = bn * BN + n0 + nf * 8 + qc * 2;
            const float2 bv = *(const float2*)(bias + gn);
            float* p0 = out + (size_t)gm * row_stride + (size_t)bz * OUTF + gn;
            float* p1 = p0 + 8 * row_stride;
            float2 v0 = { acc[mf][nf][0] + bv.x, acc[mf][nf][1] + bv.y };
            float2 v1 = { acc[mf][nf][2] + bv.x, acc[mf][nf][3] + bv.y };
            *(float2*)p0 = v0;
            *(float2*)p1 = v1;
        }
    }
}

// ---------------- launch ----------------
extern "C" void kernel_launch(void* const* d_in, const int* in_sizes, int n_in,
                              void* d_out, int out_size) {
    const float *x = nullptr, *W = nullptr, *Bl = nullptr;
    for (int i = 0; i < n_in; i++) {
        long long s = in_sizes[i];
        if (s == (long long)NROWS * INF)          x  = (const float*)d_in[i];
        else if (s == 3LL * OUTF * INF)           W  = (const float*)d_in[i];
        else if (s == 3LL * OUTF)                 Bl = (const float*)d_in[i];
    }
    float* out = (float*)d_out;

    prep_w_kernel<<<(unsigned)(((size_t)OUTF * INF / 4 + 255) / 256), 256>>>(W);
    prep_x_kernel<<<(unsigned)(((size_t)NROWS * INF / 4 + 255) / 256), 256>>>(x);
    prep_b_kernel<<<(OUTF + 255) / 256, 256>>>(Bl);

    cudaFuncSetAttribute(gemm_kernel, cudaFuncAttributeMaxDynamicSharedMemorySize, SMEM_ALLOC);
    dim3 grid(OUTF / BN, NROWS / BM, 2);  // (32, 16, 2) = 1024 CTAs
    gemm_kernel<<<grid, 256, SMEM_ALLOC>>>(out);
}